// round 1
// baseline (speedup 1.0000x reference)
#include <cuda_runtime.h>
#include <cuda_bf16.h>

// ---------------------------------------------------------------------------
// NeuralMapCell pipeline, fp32 throughout.
// Inputs (metadata order):
//  0: inputs        (1,128)            f32
//  1: memory        (4096,256)         f32
//  2: conv_kernel1  (3,3,256,32)       f32
//  3: conv_kernel2  (3,3,32,64)        f32
//  4: conv_dense1   (238144,128)       f32
//  5: conv_dense2   (128,256)          f32
//  6: context_kernel(384,256)          f32
//  7: recurr_kernel (384,256)          f32
//  8: x (int32, 1)   9: y (int32, 1)
// Output: concat( c_t[256], r_t[256], new_mem[256*4096] ) = 1049088 f32
// ---------------------------------------------------------------------------

#define H 64
#define W 64
#define UNITS 256
#define C1OC 32
#define C2OC 64
#define H2 62            // conv2 VALID output
#define HP 61            // pool output
#define FLAT (64*61*61)  // 238144
#define NPIX 4096
#define D1BLK 512
#define CTBLK 64

// Scratch (device globals; no allocation allowed)
__device__ float g_c1[H*W*C1OC];        // [h][w][oc]
__device__ float g_c2[C2OC*H2*H2];      // [oc][h2][w2]
__device__ float g_flat[FLAT];          // [oc][h][w] of pool
__device__ float g_part1[D1BLK*128];
__device__ float g_rt[256];
__device__ float g_qt[256];
__device__ float g_st[256];
__device__ float g_scores[NPIX];
__device__ float g_expv[NPIX];
__device__ float g_invsum;
__device__ float g_partC[CTBLK*256];

// ---------------------------------------------------------------------------
// conv1: SAME 3x3, 256 -> 32 channels over 64x64.
// Block = 4x4 output tile, 256 threads. Input halo (6x6 pixels x 256ch) in smem.
// ---------------------------------------------------------------------------
__global__ __launch_bounds__(256) void conv1_kernel(
    const float* __restrict__ mem, const float* __restrict__ w1)
{
    __shared__ float sin[36*256];   // [p=ph*6+pw][ic] -> 36 KB
    const int bw = blockIdx.x * 4;
    const int bh = blockIdx.y * 4;
    const int t = threadIdx.x;

    // Load 36 pixels x 256 ch as float4 (64 float4 per pixel)
    for (int idx = t; idx < 36*64; idx += 256) {
        int p = idx >> 6;
        int q = idx & 63;
        int ph = p / 6, pw = p % 6;
        int h = bh + ph - 1, w = bw + pw - 1;
        float4 v = make_float4(0.f,0.f,0.f,0.f);
        if (h >= 0 && h < H && w >= 0 && w < W)
            v = reinterpret_cast<const float4*>(mem + (h*W + w)*UNITS)[q];
        reinterpret_cast<float4*>(sin + p*256)[q] = v;
    }
    __syncthreads();

    const int oc = t & 31;
    const int pg = t >> 5;          // 0..7, each handles 2 pixels of the 4x4 tile
    const int p0 = pg*2, p1 = pg*2 + 1;
    const int ph0 = p0 >> 2, pw0 = p0 & 3;
    const int ph1 = p1 >> 2, pw1 = p1 & 3;

    float acc0 = 0.f, acc1 = 0.f;
    #pragma unroll
    for (int kh = 0; kh < 3; kh++) {
        #pragma unroll
        for (int kw = 0; kw < 3; kw++) {
            const float* __restrict__ wp = w1 + ((kh*3 + kw)*256)*32 + oc;
            const float* __restrict__ s0 = sin + ((ph0+kh)*6 + (pw0+kw))*256;
            const float* __restrict__ s1 = sin + ((ph1+kh)*6 + (pw1+kw))*256;
            #pragma unroll 8
            for (int ic = 0; ic < 256; ic++) {
                float wv = __ldg(wp + ic*32);
                acc0 += wv * s0[ic];
                acc1 += wv * s1[ic];
            }
        }
    }
    g_c1[((bh+ph0)*W + (bw+pw0))*C1OC + oc] = acc0;
    g_c1[((bh+ph1)*W + (bw+pw1))*C1OC + oc] = acc1;
}

// ---------------------------------------------------------------------------
// conv2: VALID 3x3, 32 -> 64 channels, output 62x62.
// Block = 4x8 output tile (rows pg, cols 0..7), 256 threads.
// ---------------------------------------------------------------------------
__global__ __launch_bounds__(256) void conv2_kernel(
    const float* __restrict__ w2)
{
    __shared__ float s2[60*32];     // [p=ph*10+pw][ic], 6x10 pixel halo
    const int bw = blockIdx.x * 8;
    const int bh = blockIdx.y * 4;
    const int t = threadIdx.x;

    for (int idx = t; idx < 60*8; idx += 256) {   // 8 float4 per pixel
        int p = idx >> 3;
        int q = idx & 7;
        int ph = p / 10, pw = p % 10;
        int h = bh + ph, w = bw + pw;
        float4 v = make_float4(0.f,0.f,0.f,0.f);
        if (h < H && w < W)
            v = reinterpret_cast<const float4*>(g_c1 + (h*W + w)*C1OC)[q];
        reinterpret_cast<float4*>(s2 + p*32)[q] = v;
    }
    __syncthreads();

    const int oc = t & 63;
    const int pg = t >> 6;          // output row within the 4x8 tile
    float acc[8];
    #pragma unroll
    for (int i = 0; i < 8; i++) acc[i] = 0.f;

    #pragma unroll
    for (int kh = 0; kh < 3; kh++) {
        #pragma unroll
        for (int kw = 0; kw < 3; kw++) {
            const float* __restrict__ wp = w2 + ((kh*3 + kw)*32)*64 + oc;
            const float* __restrict__ sp = s2 + ((pg+kh)*10 + kw)*32;
            #pragma unroll 4
            for (int ic = 0; ic < 32; ic++) {
                float wv = __ldg(wp + ic*64);
                #pragma unroll
                for (int pw = 0; pw < 8; pw++)
                    acc[pw] += wv * sp[pw*32 + ic];
            }
        }
    }
    const int h2 = bh + pg;
    if (h2 < H2) {
        #pragma unroll
        for (int pw = 0; pw < 8; pw++) {
            int w2i = bw + pw;
            if (w2i < H2)
                g_c2[oc*(H2*H2) + h2*H2 + w2i] = acc[pw];
        }
    }
}

// ---------------------------------------------------------------------------
// 2x2 sum pool (stride 1) * 0.25 -> flat (oc-major, 61x61)
// ---------------------------------------------------------------------------
__global__ __launch_bounds__(256) void pool_kernel()
{
    int idx = blockIdx.x * 256 + threadIdx.x;
    if (idx >= FLAT) return;
    int oc = idx / (HP*HP);
    int r = idx - oc*(HP*HP);
    int h = r / HP;
    int w = r - h*HP;
    const float* base = g_c2 + oc*(H2*H2) + h*H2 + w;
    g_flat[idx] = 0.25f * (base[0] + base[1] + base[H2] + base[H2+1]);
}

// ---------------------------------------------------------------------------
// dense1 partials: flat (1x238144) @ W1 (238144x128) -> 512 partial 128-vectors
// ---------------------------------------------------------------------------
__global__ __launch_bounds__(256) void dense1_kernel(const float* __restrict__ W1)
{
    const int t = threadIdx.x;
    const int j = t & 127;
    const int r = t >> 7;           // 0/1: two rows per iteration
    const int base = blockIdx.x * 466;
    float acc = 0.f;
    #pragma unroll 4
    for (int it = 0; it < 233; it++) {
        int i = base + it*2 + r;
        if (i < FLAT)
            acc += g_flat[i] * __ldg(W1 + (long)i*128 + j);
    }
    __shared__ float sred[256];
    sred[t] = acc;
    __syncthreads();
    if (t < 128)
        g_part1[blockIdx.x*128 + t] = sred[t] + sred[t + 128];
}

// ---------------------------------------------------------------------------
// Fused small math: reduce r128; r_t = r128@W2; q_t = [in,r_t]@ctx; s_t = in@rec[:128]
// Single block, 256 threads.
// ---------------------------------------------------------------------------
__global__ __launch_bounds__(256) void fuse1_kernel(
    const float* __restrict__ inputs, const float* __restrict__ W2,
    const float* __restrict__ ctx, const float* __restrict__ rec)
{
    __shared__ float s_r128[128];
    __shared__ float s_rt[256];
    __shared__ float s_in[128];
    const int t = threadIdx.x;

    if (t < 128) {
        float a = 0.f;
        for (int b = 0; b < D1BLK; b++) a += g_part1[b*128 + t];
        s_r128[t] = a;
        s_in[t] = inputs[t];
    }
    __syncthreads();

    float rt = 0.f;
    #pragma unroll 8
    for (int k = 0; k < 128; k++) rt += s_r128[k] * W2[k*256 + t];
    s_rt[t] = rt;
    g_rt[t] = rt;
    __syncthreads();

    float q = 0.f, sv = 0.f;
    #pragma unroll 8
    for (int k = 0; k < 128; k++) {
        float iv = s_in[k];
        q  += iv * ctx[k*256 + t];
        sv += iv * rec[k*256 + t];
    }
    #pragma unroll 8
    for (int k = 0; k < 256; k++)
        q += s_rt[k] * ctx[(128 + k)*256 + t];
    g_qt[t] = q;
    g_st[t] = sv;
}

// ---------------------------------------------------------------------------
// scores[p] = dot(q_t, memory[p,:])  — warp per row
// ---------------------------------------------------------------------------
__global__ __launch_bounds__(256) void scores_kernel(const float* __restrict__ mem)
{
    __shared__ float4 sq[64];
    const int t = threadIdx.x;
    if (t < 64) sq[t] = reinterpret_cast<const float4*>(g_qt)[t];
    __syncthreads();

    const int lane = t & 31;
    const int p = blockIdx.x * 8 + (t >> 5);
    const float4* mp = reinterpret_cast<const float4*>(mem + p*UNITS);
    float4 m0 = mp[lane];
    float4 m1 = mp[lane + 32];
    float4 q0 = sq[lane];
    float4 q1 = sq[lane + 32];
    float acc = m0.x*q0.x + m0.y*q0.y + m0.z*q0.z + m0.w*q0.w
              + m1.x*q1.x + m1.y*q1.y + m1.z*q1.z + m1.w*q1.w;
    #pragma unroll
    for (int o = 16; o > 0; o >>= 1)
        acc += __shfl_down_sync(0xffffffffu, acc, o);
    if (lane == 0) g_scores[p] = acc;
}

// ---------------------------------------------------------------------------
// softmax over 4096 scores (single block) -> expv + 1/sum
// ---------------------------------------------------------------------------
__global__ __launch_bounds__(1024) void softmax_kernel()
{
    __shared__ float red[32];
    const int t = threadIdx.x;
    float4 v = reinterpret_cast<const float4*>(g_scores)[t];
    float m = fmaxf(fmaxf(v.x, v.y), fmaxf(v.z, v.w));
    #pragma unroll
    for (int o = 16; o > 0; o >>= 1)
        m = fmaxf(m, __shfl_xor_sync(0xffffffffu, m, o));
    if ((t & 31) == 0) red[t >> 5] = m;
    __syncthreads();
    if (t < 32) {
        float mm = red[t];
        #pragma unroll
        for (int o = 16; o > 0; o >>= 1)
            mm = fmaxf(mm, __shfl_xor_sync(0xffffffffu, mm, o));
        red[t] = mm;
    }
    __syncthreads();
    const float gmax = red[0];
    __syncthreads();

    float4 e;
    e.x = expf(v.x - gmax); e.y = expf(v.y - gmax);
    e.z = expf(v.z - gmax); e.w = expf(v.w - gmax);
    reinterpret_cast<float4*>(g_expv)[t] = e;
    float s = e.x + e.y + e.z + e.w;
    #pragma unroll
    for (int o = 16; o > 0; o >>= 1)
        s += __shfl_xor_sync(0xffffffffu, s, o);
    if ((t & 31) == 0) red[t >> 5] = s;
    __syncthreads();
    if (t == 0) {
        float ss = 0.f;
        for (int i = 0; i < 32; i++) ss += red[i];
        g_invsum = 1.f / ss;
    }
}

// ---------------------------------------------------------------------------
// c_t partials: sum_p expv[p] * memory[p,:], 64 blocks of 64 rows
// ---------------------------------------------------------------------------
__global__ __launch_bounds__(256) void ctpart_kernel(const float* __restrict__ mem)
{
    const int c = threadIdx.x;
    const int base = blockIdx.x * 64;
    float acc = 0.f;
    #pragma unroll 4
    for (int p = base; p < base + 64; p++)
        acc += g_expv[p] * __ldg(mem + p*UNITS + c);
    g_partC[blockIdx.x*256 + c] = acc;
}

// ---------------------------------------------------------------------------
// Transpose memory (4096,256) -> new_mem (256,4096) region of out
// ---------------------------------------------------------------------------
__global__ __launch_bounds__(256) void transpose_kernel(
    const float* __restrict__ mem, float* __restrict__ out)
{
    __shared__ float tile[32][33];
    const int p0 = blockIdx.x * 32;
    const int c0 = blockIdx.y * 32;
    const int tx = threadIdx.x, ty = threadIdx.y;
    #pragma unroll
    for (int j = ty; j < 32; j += 8)
        tile[j][tx] = mem[(p0 + j)*UNITS + c0 + tx];
    __syncthreads();
    #pragma unroll
    for (int j = ty; j < 32; j += 8)
        out[512 + (size_t)(c0 + j)*NPIX + p0 + tx] = tile[tx][j];
}

// ---------------------------------------------------------------------------
// Final: reduce c_t, imps, mem_t update at (x,y); write c_t and r_t to out
// ---------------------------------------------------------------------------
__global__ __launch_bounds__(256) void final_kernel(
    const float* __restrict__ mem, const float* __restrict__ rec,
    const int* __restrict__ px, const int* __restrict__ py,
    float* __restrict__ out)
{
    __shared__ float s_ct[256], s_st[256], s_mold[256];
    __shared__ float red[16];
    __shared__ float s_frac;
    const int c = threadIdx.x;
    const int pos = px[0]*W + py[0];

    float ct = 0.f;
    for (int b = 0; b < CTBLK; b++) ct += g_partC[b*256 + c];
    ct *= g_invsum;
    float rt = g_rt[c];
    float st = g_st[c];
    s_ct[c] = ct;
    s_st[c] = st;
    s_mold[c] = mem[pos*UNITS + c];
    out[c] = ct;
    out[256 + c] = rt;

    // reduce local_imp = sum(st*ct), global_imp = sum(st*rt)
    float li = st * ct;
    float gi = st * rt;
    #pragma unroll
    for (int o = 16; o > 0; o >>= 1) {
        li += __shfl_xor_sync(0xffffffffu, li, o);
        gi += __shfl_xor_sync(0xffffffffu, gi, o);
    }
    if ((c & 31) == 0) {
        red[c >> 5] = li;
        red[8 + (c >> 5)] = gi;
    }
    __syncthreads();
    if (c == 0) {
        float L = 0.f, G = 0.f;
        for (int i = 0; i < 8; i++) { L += red[i]; G += red[8 + i]; }
        s_frac = L / (L + G);
    }
    __syncthreads();

    const float frac = s_frac;
    float d = 0.f;
    #pragma unroll 8
    for (int k = 0; k < 256; k++)
        d += (s_mold[k] - s_st[k]) * rec[(128 + k)*256 + c];
    out[512 + (size_t)c*NPIX + pos] = s_mold[c] + frac * d;
}

// ---------------------------------------------------------------------------
extern "C" void kernel_launch(void* const* d_in, const int* in_sizes, int n_in,
                              void* d_out, int out_size)
{
    const float* inputs = (const float*)d_in[0];
    const float* mem    = (const float*)d_in[1];
    const float* ck1    = (const float*)d_in[2];
    const float* ck2    = (const float*)d_in[3];
    const float* cd1    = (const float*)d_in[4];
    const float* cd2    = (const float*)d_in[5];
    const float* ctx    = (const float*)d_in[6];
    const float* rec    = (const float*)d_in[7];
    const int*   px     = (const int*)d_in[8];
    const int*   py     = (const int*)d_in[9];
    float* out = (float*)d_out;

    conv1_kernel<<<dim3(16, 16), 256>>>(mem, ck1);
    conv2_kernel<<<dim3(8, 16), 256>>>(ck2);
    pool_kernel<<<(FLAT + 255) / 256, 256>>>();
    dense1_kernel<<<D1BLK, 256>>>(cd1);
    fuse1_kernel<<<1, 256>>>(inputs, cd2, ctx, rec);
    scores_kernel<<<NPIX / 8, 256>>>(mem);
    softmax_kernel<<<1, 1024>>>();
    ctpart_kernel<<<CTBLK, 256>>>(mem);
    transpose_kernel<<<dim3(NPIX / 32, UNITS / 32), dim3(32, 8)>>>(mem, out);
    final_kernel<<<1, 256>>>(mem, rec, px, py, out);
}